// round 7
// baseline (speedup 1.0000x reference)
#include <cuda_runtime.h>
#include <math.h>

#define BB 4
#define LL 512
#define VV 32128
#define AVV 32000
#define DD 768
#define NT (BB*LL)
#define NV4 (VV/4)      // 8032
#define ND4 (DD/4)      // 192
#define NTH 256
#define CH 4            // chunks per token
#define CV4 (NV4/CH)    // 2008 float4 per chunk

// Scratch (device globals; no allocation allowed)
__device__ int4 g_part[NT * CH];   // per (token,chunk) top-2: {bits(v1),i1,bits(v2),i2}
__device__ int  g_am[NT];          // final embed row (-1 = masked)
__device__ int  g_ps[NT];          // psg row (-1 = none)

// ---------------------------------------------------------------------------
// Exact coarse key: lo - log(-log u). Series path near u=1: winners have
// u ~ 1-3e-5 where __logf's ~1e-6 ABSOLUTE error would be catastrophic
// relative error on t = -log u. Abs key error bounded ~1.2e-4.
// ---------------------------------------------------------------------------
__device__ __forceinline__ float coarse_key(float lo, float u) {
    float w  = 1.0f - u;                 // exact for u > 0.5 (Sterbenz)
    float ts = fmaf(0.5f * w, w, w);     // w + w^2/2
    float tl = -__logf(u);
    float t  = (u > 0.99609375f) ? ts : tl;
    return lo - __logf(t);
}

__device__ __forceinline__ double precise_key(float lo, float u) {
    return (double)lo - log(-log((double)u));
}

__device__ __forceinline__ void ins2(float k, int j,
                                     float& v1, int& i1,
                                     float& v2, int& i2) {
    bool p = k > v1;
    float dv = p ? v1 : k;
    int   di = p ? i1 : j;
    if (p) { v1 = k; i1 = j; }
    if (dv > v2) { v2 = dv; i2 = di; }
}

__device__ __forceinline__ void top2_insert(float w, int j,
                                            float& v1, int& i1,
                                            float& v2, int& i2) {
    if (w > v1 || (w == v1 && j < i1)) {
        v2 = v1; i2 = i1; v1 = w; i1 = j;
    } else if (w > v2 || (w == v2 && j < i2)) {
        v2 = w; i2 = j;
    }
}

// Conservative u-threshold: u <= uthr  =>  key <= thr  (given lo <= rmax).
// 1-uthr >= exp(rmax-thr) with margins for __expf (2 ulp) and the subtract.
__device__ __forceinline__ float make_uthr(float rmax, float thr) {
    float t = __expf(rmax - thr);
    return 1.0f - fmaf(t, 1.00002f, 1e-6f);
}

// ---------------------------------------------------------------------------
// K0: psg prep. One warp per batch, shuffle reductions only.
// ---------------------------------------------------------------------------
__global__ void __launch_bounds__(32)
psg_prep_kernel(const int* __restrict__ rwrt,
                const int* __restrict__ psg_in) {
    __shared__ int s_r[LL];
    __shared__ int s_p[LL];
    const int b    = blockIdx.x;
    const int lane = threadIdx.x;

    int cnt = 0;
#pragma unroll
    for (int k = 0; k < LL / 32; k++) {
        int l  = lane + 32 * k;
        int rv = rwrt[b * LL + l];
        s_r[l] = rv;
        s_p[l] = psg_in[b * LL + l];
        cnt += (rv == 1);
    }
    __syncwarp();
#pragma unroll
    for (int o = 16; o > 0; o >>= 1) cnt += __shfl_xor_sync(0xFFFFFFFFu, cnt, o);
    const int shift = cnt;

    int tr[LL / 32];
    int firstnz = LL;
#pragma unroll
    for (int k = 0; k < LL / 32; k++) {
        int l   = lane + 32 * k;
        int pos = ((l - shift) % LL + LL) % LL;
        int fm  = 1 - s_r[LL - 1 - pos];
        int psv = (pos == 0) ? 1 : s_p[pos - 1];
        int t   = fm * psv;
        tr[k] = t;
        if (t != 0) firstnz = min(firstnz, l);
    }
#pragma unroll
    for (int o = 16; o > 0; o >>= 1)
        firstnz = min(firstnz, __shfl_xor_sync(0xFFFFFFFFu, firstnz, o));

#pragma unroll
    for (int k = 0; k < LL / 32; k++) {
        int l = lane + 32 * k;
        g_ps[b * LL + l] = (l >= firstnz) ? tr[k] : -1;
    }
}

// ---------------------------------------------------------------------------
// K1: streaming scan, ALU-minimal filter (6 FMAX + 2 FSETP per float4).
// ---------------------------------------------------------------------------
__global__ void __launch_bounds__(NTH)
scan_kernel(const float* __restrict__ logits,
            const float* __restrict__ gu) {
    const int blk = blockIdx.x;
    const int t   = blk >> 2;
    const int c   = blk & 3;
    const int tid = threadIdx.x;

    const float4* lg = (const float4*)(logits + (size_t)t * VV) + c * CV4;
    const float4* gg = (const float4*)(gu     + (size_t)t * VV) + c * CV4;
    const int jbase = c * CV4 * 4;

    float v1 = -INFINITY, v2 = -INFINITY;
    int   i1 = 0,         i2 = 1;
    float rmax;

    // ---- seed: one exact float4 per thread ----
    {
        float4 a = __ldcs(lg + tid);
        float4 g = __ldcs(gg + tid);
        int base = jbase + 4 * tid;
        ins2(coarse_key(a.x, g.x), base + 0, v1, i1, v2, i2);
        ins2(coarse_key(a.y, g.y), base + 1, v1, i1, v2, i2);
        ins2(coarse_key(a.z, g.z), base + 2, v1, i1, v2, i2);
        ins2(coarse_key(a.w, g.w), base + 3, v1, i1, v2, i2);
        rmax = fmaxf(fmaxf(a.x, a.y), fmaxf(a.z, a.w));
    }

    // ---- block-wide seed reduce: thr = 2nd-max key, rmax = max logit ----
    __shared__ float s_v1[NTH];
    __shared__ float s_v2[NTH];
    __shared__ float s_rm[NTH];
    __shared__ int   s_i1[NTH];
    __shared__ int   s_i2[NTH];
    s_v1[tid] = v1; s_v2[tid] = v2; s_rm[tid] = rmax;
    __syncthreads();
    for (int s = NTH / 2; s > 0; s >>= 1) {
        if (tid < s) {
            float b1 = s_v1[tid + s], b2 = s_v2[tid + s];
            float a1 = s_v1[tid],     a2 = s_v2[tid];
            float hi  = fmaxf(a1, b1);
            float lo2 = fmaxf(fminf(a1, b1), fmaxf(a2, b2));
            s_v1[tid] = hi; s_v2[tid] = lo2;
            s_rm[tid] = fmaxf(s_rm[tid], s_rm[tid + s]);
        }
        __syncthreads();
    }
    float thr = fmaxf(v2, s_v2[0]);   // lower bound on chunk #2
    rmax = s_rm[0];                   // upper bound on logits seen so far
    float uthr = make_uthr(rmax, thr);
    __syncthreads();                  // smem reused below

    // ---- main loop: 2 LDG + 6 FMAX + 2 FSETP per float4 ----
    for (int i = tid + NTH; i < CV4; i += NTH) {
        float4 a = __ldcs(lg + i);
        float4 g = __ldcs(gg + i);
        float um = fmaxf(fmaxf(g.x, g.y), fmaxf(g.z, g.w));
        float lm = fmaxf(fmaxf(a.x, a.y), fmaxf(a.z, a.w));
        if (um > uthr || lm > rmax) {
            int base = jbase + 4 * i;
            ins2(coarse_key(a.x, g.x), base + 0, v1, i1, v2, i2);
            ins2(coarse_key(a.y, g.y), base + 1, v1, i1, v2, i2);
            ins2(coarse_key(a.z, g.z), base + 2, v1, i1, v2, i2);
            ins2(coarse_key(a.w, g.w), base + 3, v1, i1, v2, i2);
            rmax = fmaxf(rmax, lm);
            thr  = fmaxf(thr, v2);
            uthr = make_uthr(rmax, thr);
        }
    }

    // ---- block top-2 reduction with index tie-break ----
    s_v1[tid] = v1; s_i1[tid] = i1;
    s_v2[tid] = v2; s_i2[tid] = i2;
    __syncthreads();
    for (int s = NTH / 2; s > 0; s >>= 1) {
        if (tid < s) {
            float w1 = s_v1[tid + s], w2 = s_v2[tid + s];
            int   j1 = s_i1[tid + s], j2 = s_i2[tid + s];
            float a1 = s_v1[tid],     a2 = s_v2[tid];
            int   c1 = s_i1[tid],     c2 = s_i2[tid];
            top2_insert(w1, j1, a1, c1, a2, c2);
            top2_insert(w2, j2, a1, c1, a2, c2);
            s_v1[tid] = a1; s_i1[tid] = c1;
            s_v2[tid] = a2; s_i2[tid] = c2;
        }
        __syncthreads();
    }
    if (tid == 0) {
        g_part[blk] = make_int4(__float_as_int(s_v1[0]), s_i1[0],
                                __float_as_int(s_v2[0]), s_i2[0]);
    }
}

// ---------------------------------------------------------------------------
// K2: decide. 8 blocks x 256: one thread per token. Merges 4 partials,
// fp64 near-tie recheck, folds rwrt/AV mask into g_am.
// ---------------------------------------------------------------------------
__global__ void __launch_bounds__(NTH)
decide_kernel(const float* __restrict__ logits,
              const float* __restrict__ gu,
              const int*   __restrict__ rwrt) {
    const int t = blockIdx.x * NTH + threadIdx.x;   // 0..NT-1

    float v1 = -INFINITY, v2 = -INFINITY;
    int   i1 = 0,         i2 = 1;
#pragma unroll
    for (int cc = 0; cc < CH; cc++) {
        int4 pr = g_part[t * CH + cc];
        top2_insert(__int_as_float(pr.x), pr.y, v1, i1, v2, i2);
        top2_insert(__int_as_float(pr.z), pr.w, v1, i1, v2, i2);
    }
    int win = i1;
    if (v1 - v2 < 0.02f) {
        double k1 = precise_key(logits[(size_t)t * VV + i1],
                                gu[(size_t)t * VV + i1]);
        double k2 = precise_key(logits[(size_t)t * VV + i2],
                                gu[(size_t)t * VV + i2]);
        if (k2 > k1 || (k2 == k1 && i2 < i1)) win = i2;
    }
    g_am[t] = (rwrt[t] != 0 && win < AVV) ? win : -1;
}

// ---------------------------------------------------------------------------
// K3: pure gather. One float4 per thread, no smem, no barriers. 1536 blocks.
// ---------------------------------------------------------------------------
__global__ void __launch_bounds__(NTH)
gather_kernel(const float* __restrict__ W,
              float*       __restrict__ out) {
    const int idx = blockIdx.x * NTH + threadIdx.x;   // 0 .. NT*ND4-1
    const int t   = idx / ND4;
    const int d   = idx - t * ND4;

    const float4* W4 = (const float4*)W;
    int am = __ldg(&g_am[t]);
    int ps = __ldg(&g_ps[t]);

    float4 acc = make_float4(0.f, 0.f, 0.f, 0.f);
    if (am >= 0) acc = W4[(size_t)am * ND4 + d];
    if (ps >= 0) {
        float4 wv = W4[(size_t)ps * ND4 + d];
        acc.x += wv.x; acc.y += wv.y; acc.z += wv.z; acc.w += wv.w;
    }
    ((float4*)out)[idx] = acc;
}

// ---------------------------------------------------------------------------
extern "C" void kernel_launch(void* const* d_in, const int* in_sizes, int n_in,
                              void* d_out, int out_size) {
    const float* logits = (const float*)d_in[0];
    const float* gu     = (const float*)d_in[1];
    const float* W      = (const float*)d_in[2];
    const int*   rwrt   = (const int*)d_in[3];
    const int*   psg    = (const int*)d_in[4];
    float* out = (float*)d_out;

    psg_prep_kernel<<<BB, 32>>>(rwrt, psg);
    scan_kernel<<<NT * CH, NTH>>>(logits, gu);
    decide_kernel<<<NT / NTH, NTH>>>(logits, gu, rwrt);
    gather_kernel<<<(NT * ND4) / NTH, NTH>>>(W, out);
}